// round 10
// baseline (speedup 1.0000x reference)
#include <cuda_runtime.h>
#include <math.h>

// Problem constants
#define BN   8192
#define DN   64
#define CTXN 256
#define HN   512
#define ROWS 32        // rows per CTA
#define NTHR 256
#define CTXP 36        // padded row-stride for staged context (144B, 16B-aligned)

typedef unsigned long long u64;

// ---------------- static device scratch (no allocations allowed) -------------
__device__ __align__(16) float g_W2r[HN * HN];    // [k_in][n_out], permuted+masked
__device__ __align__(16) float g_W1r[DN * HN];    // [input d][p], permuted+masked
__device__ __align__(16) float g_WomMu[DN * HN];  // [step i][p]
__device__ __align__(16) float g_WomSc[DN * HN];  // [step i][p]
__device__ __align__(16) float g_Wcr[CTXN * HN];  // [c][p] permuted Wc
__device__ __align__(16) float g_b1r[HN];
__device__ __align__(16) float g_b2r[HN];
// per-step chunk schedule: [step][warp-bin][slot] = (blk<<1)|rowhalf, 0xFF = empty
__device__ __align__(4) unsigned char g_sched[DN][8][4];

// ------------- degree-sorted permutation (analytic) --------------------------
// mh[h] = h % 63 + 1 ; degrees 1..8 appear 9x, 9..63 appear 8x.
__device__ __forceinline__ int degp(int p) { return (p < 72) ? (p / 9 + 1) : (p / 8); }
__device__ __forceinline__ int origp(int p) {
    int d, j;
    if (p < 72) { d = p / 9 + 1; j = p - 9 * (d - 1); }
    else        { d = p / 8;     j = p - 8 * d; }
    return (d - 1) + 63 * j;
}
__device__ __forceinline__ int cntd(int d) {
    return (d <= 0) ? 0 : ((d <= 8) ? 9 * d : 8 * d + 8);
}
// max nonzero k for degree block b (64 units per block)
__device__ __forceinline__ int kwblk(int b) { return (b == 0) ? 72 : 64 * (b + 1); }

// ------------- packed f32x2 helpers ------------------------------------------
__device__ __forceinline__ u64 dup2(float a) {
    u64 r; asm("mov.b64 %0, {%1, %1};" : "=l"(r) : "f"(a)); return r;
}
__device__ __forceinline__ void fma2(u64& d, u64 a, u64 b) {
    asm("fma.rn.f32x2 %0, %1, %2, %0;" : "+l"(d) : "l"(a), "l"(b));
}
__device__ __forceinline__ void unpk(u64 v, float& a, float& b) {
    asm("mov.b64 {%0, %1}, %2;" : "=f"(a), "=f"(b) : "l"(v));
}

// ------------- weight preparation + schedule ----------------------------------
__global__ void prep_kernel(const float* __restrict__ W1, const float* __restrict__ b1,
                            const float* __restrict__ Wc, const float* __restrict__ W2,
                            const float* __restrict__ b2, const float* __restrict__ Wo) {
    int idx = blockIdx.x * blockDim.x + threadIdx.x;
    if (idx < HN * HN) {
        int k = idx / HN, n = idx % HN;
        int dn = degp(n), dk = degp(k);
        g_W2r[idx] = (dn >= dk) ? W2[origp(n) * HN + origp(k)] : 0.f;
    }
    if (idx < DN * HN) {
        int i = idx / HN, p = idx % HN;
        int dp = degp(p), op = origp(p);
        g_W1r[idx]   = (dp >= i + 1) ? W1[op * DN + i] : 0.f;
        bool m = (dp <= i);
        g_WomMu[idx] = m ? Wo[i * HN + op] : 0.f;
        g_WomSc[idx] = m ? Wo[(DN + i) * HN + op] : 0.f;
    }
    if (idx < CTXN * HN) {
        int c = idx / HN, p = idx % HN;
        g_Wcr[idx] = Wc[origp(p) * CTXN + c];
    }
    if (idx < HN) {
        int op = origp(idx);
        g_b1r[idx] = b1[op];
        g_b2r[idx] = b2[op];
    }
    if (idx == 0) {
        // LPT schedule: per step, chunks = (active block) x (2 row-halves),
        // work = kw; assign descending to least-loaded of 8 bins.
        for (int i = 0; i < DN; i++) {
            int ncur = cntd(i);
            int na = (ncur + 63) >> 6;
            int loadv[8], cnt[8];
            for (int j = 0; j < 8; j++) { loadv[j] = 0; cnt[j] = 0; }
            for (int w = 0; w < 8; w++)
                for (int s = 0; s < 4; s++) g_sched[i][w][s] = 0xFF;
            for (int b = na - 1; b >= 0; b--) {
                int kw = kwblk(b); if (kw > ncur) kw = ncur;
                for (int h = 0; h < 2; h++) {
                    int best = -1;
                    for (int j = 0; j < 8; j++)
                        if (cnt[j] < 4 && (best < 0 || loadv[j] < loadv[best])) best = j;
                    g_sched[i][best][cnt[best]++] = (unsigned char)((b << 1) | h);
                    loadv[best] += kw;
                }
            }
        }
    }
}

// 2-k weight group: units nb0+ull*8 .. +8, rows k and k+1
struct G { ulonglong2 a0, b0, a1, b1; };
__device__ __forceinline__ void loadG(G& g, const float* wp) {
    g.a0 = *(const ulonglong2*)(wp);
    g.b0 = *(const ulonglong2*)(wp + 4);
    g.a1 = *(const ulonglong2*)(wp + HN);
    g.b1 = *(const ulonglong2*)(wp + HN + 4);
}
// acc[up*4+rr]: unit-pair up (0..3), row rr (0..3)
__device__ __forceinline__ void compute2(u64* acc, const G& g, const float* hp) {
    float4 v = *(const float4*)(hp);
    u64 h0 = dup2(v.x), h1 = dup2(v.y), h2 = dup2(v.z), h3 = dup2(v.w);
    fma2(acc[0],  g.a0.x, h0); fma2(acc[1],  g.a0.x, h1); fma2(acc[2],  g.a0.x, h2); fma2(acc[3],  g.a0.x, h3);
    fma2(acc[4],  g.a0.y, h0); fma2(acc[5],  g.a0.y, h1); fma2(acc[6],  g.a0.y, h2); fma2(acc[7],  g.a0.y, h3);
    fma2(acc[8],  g.b0.x, h0); fma2(acc[9],  g.b0.x, h1); fma2(acc[10], g.b0.x, h2); fma2(acc[11], g.b0.x, h3);
    fma2(acc[12], g.b0.y, h0); fma2(acc[13], g.b0.y, h1); fma2(acc[14], g.b0.y, h2); fma2(acc[15], g.b0.y, h3);
    float4 w = *(const float4*)(hp + ROWS);
    h0 = dup2(w.x); h1 = dup2(w.y); h2 = dup2(w.z); h3 = dup2(w.w);
    fma2(acc[0],  g.a1.x, h0); fma2(acc[1],  g.a1.x, h1); fma2(acc[2],  g.a1.x, h2); fma2(acc[3],  g.a1.x, h3);
    fma2(acc[4],  g.a1.y, h0); fma2(acc[5],  g.a1.y, h1); fma2(acc[6],  g.a1.y, h2); fma2(acc[7],  g.a1.y, h3);
    fma2(acc[8],  g.b1.x, h0); fma2(acc[9],  g.b1.x, h1); fma2(acc[10], g.b1.x, h2); fma2(acc[11], g.b1.x, h3);
    fma2(acc[12], g.b1.y, h0); fma2(acc[13], g.b1.y, h1); fma2(acc[14], g.b1.y, h2); fma2(acc[15], g.b1.y, h3);
}

// ------------- main persistent kernel ----------------------------------------
// Phase 2 work unit: chunk = (degree block, 16-row half). Static LPT schedule
// in g_sched maps chunks -> 8 warp bins per step. No cross-warp combines
// needed (rows independent through relu + mu/sc epilogue).
// Lane layout: ull = lane&7 (8 units each), rg = lane>>3 (4 rows each).
__global__ void __launch_bounds__(NTHR, 2)
made_kernel(const float* __restrict__ ctx, const float* __restrict__ eps,
            const float* __restrict__ bo, float* __restrict__ out) {
    extern __shared__ float smem[];
    float* a1f  = smem;                    // [HN][ROWS]: prefix relu'd, suffix raw
    float* zbuf = smem + HN * ROWS;        // [ROWS]
    float* red  = zbuf + ROWS;             // [8 blk][32 row][2]

    const int t    = threadIdx.x;
    const int wid  = t >> 5;
    const int lane = t & 31;
    const int rg   = lane >> 3;
    const int ull  = lane & 7;
    const int widr = (wid + (blockIdx.x & 1)) & 7;   // CTA-parity bin rotation
    const int row0 = blockIdx.x * ROWS;

    // ---- Phase 0: stage context transposed into SMEM (stride CTXP=36) ----
    for (int idx = t; idx < CTXN * ROWS; idx += NTHR) {
        int r = idx >> 8;
        int c = idx & 255;
        a1f[c * CTXP + r] = ctx[(row0 + r) * CTXN + c];
    }
    __syncthreads();

    // ---- Phase 1: ctx GEMM -> a1 init (8 units x 8 rows per lane) ----
    {
        const int nbase1 = wid * 64 + ull * 8;
        const int r0t    = rg * 8;
        u64 acc1[4][8];
#pragma unroll
        for (int a = 0; a < 4; a++)
#pragma unroll
            for (int b = 0; b < 8; b++) acc1[a][b] = 0ull;
        const float* wp = g_Wcr + nbase1;
        const float* hp = a1f + r0t;
#pragma unroll 2
        for (int c = 0; c < CTXN; c++) {
            ulonglong2 wA = *(const ulonglong2*)(wp);
            ulonglong2 wB = *(const ulonglong2*)(wp + 4);
            wp += HN;
            float4 v0 = *(const float4*)(hp);
            float4 v1 = *(const float4*)(hp + 4);
            hp += CTXP;
            u64 h[8];
            h[0] = dup2(v0.x); h[1] = dup2(v0.y); h[2] = dup2(v0.z); h[3] = dup2(v0.w);
            h[4] = dup2(v1.x); h[5] = dup2(v1.y); h[6] = dup2(v1.z); h[7] = dup2(v1.w);
#pragma unroll
            for (int r = 0; r < 8; r++) {
                fma2(acc1[0][r], wA.x, h[r]);
                fma2(acc1[1][r], wA.y, h[r]);
                fma2(acc1[2][r], wB.x, h[r]);
                fma2(acc1[3][r], wB.y, h[r]);
            }
        }
        __syncthreads();
#pragma unroll
        for (int up = 0; up < 4; up++) {
            int n0 = nbase1 + 2 * up;
            float bA = g_b1r[n0], bB = g_b1r[n0 + 1];
#pragma unroll
            for (int rr = 0; rr < 8; rr++) {
                float lo, hi; unpk(acc1[up][rr], lo, hi);
                int r = r0t + rr;
                a1f[n0 * ROWS + r]       = lo + bA;
                a1f[(n0 + 1) * ROWS + r] = hi + bB;
            }
        }
    }
    __syncthreads();

    // ---- Phase 2: D sequential steps ----
    for (int i = 0; i < DN; i++) {
        const int ncur = cntd(i);

        // chunk list for this warp (uniform within warp)
        const uchar4 sch = *(const uchar4*)&g_sched[i][widr][0];
        unsigned char sl[4] = {sch.x, sch.y, sch.z, sch.w};

#pragma unroll 1
        for (int s = 0; s < 4; s++) {
            unsigned char e = sl[s];
            if (e == 0xFF) break;
            const int blk  = e >> 1;
            const int half = e & 1;
            const int nb0  = blk * 64;
            int kw = kwblk(blk); if (kw > ncur) kw = ncur;

            u64 acc[16];
#pragma unroll
            for (int a = 0; a < 16; a++) acc[a] = 0ull;

            const float* wp = g_W2r + nb0 + ull * 8;
            const float* hp = a1f + half * 16 + rg * 4;
            int k = 0;
            if (kw >= 8) {
                G P, Q;
                loadG(P, wp); loadG(Q, wp + 2 * HN); wp += 4 * HN;
                for (; k + 8 <= kw; k += 4) {
                    compute2(acc, P, hp); hp += 2 * ROWS;
                    loadG(P, wp);         wp += 2 * HN;
                    compute2(acc, Q, hp); hp += 2 * ROWS;
                    loadG(Q, wp);         wp += 2 * HN;
                }
                compute2(acc, P, hp); hp += 2 * ROWS;
                compute2(acc, Q, hp); hp += 2 * ROWS;
                k += 4;
            }
            for (; k + 2 <= kw; k += 2) {
                G T; loadG(T, wp); wp += 2 * HN;
                compute2(acc, T, hp); hp += 2 * ROWS;
            }
            if (k < kw) {   // single odd k
                ulonglong2 a0 = *(const ulonglong2*)(wp);
                ulonglong2 b0 = *(const ulonglong2*)(wp + 4);
                float4 v = *(const float4*)(hp);
                u64 h0 = dup2(v.x), h1 = dup2(v.y), h2 = dup2(v.z), h3 = dup2(v.w);
                fma2(acc[0],  a0.x, h0); fma2(acc[1],  a0.x, h1); fma2(acc[2],  a0.x, h2); fma2(acc[3],  a0.x, h3);
                fma2(acc[4],  a0.y, h0); fma2(acc[5],  a0.y, h1); fma2(acc[6],  a0.y, h2); fma2(acc[7],  a0.y, h3);
                fma2(acc[8],  b0.x, h0); fma2(acc[9],  b0.x, h1); fma2(acc[10], b0.x, h2); fma2(acc[11], b0.x, h3);
                fma2(acc[12], b0.y, h0); fma2(acc[13], b0.y, h1); fma2(acc[14], b0.y, h2); fma2(acc[15], b0.y, h3);
            }

            // fused epilogue for this chunk: +b2, relu, dot Wom mu/sc
            float muP[4] = {0.f, 0.f, 0.f, 0.f};
            float scP[4] = {0.f, 0.f, 0.f, 0.f};
            const float* wm = g_WomMu + i * HN + nb0 + ull * 8;
            const float* ws = g_WomSc + i * HN + nb0 + ull * 8;
#pragma unroll
            for (int up = 0; up < 4; up++) {
                int n0 = nb0 + ull * 8 + 2 * up;
                float b2a = g_b2r[n0], b2b = g_b2r[n0 + 1];
                float wma = wm[2 * up], wmb = wm[2 * up + 1];
                float wsa = ws[2 * up], wsb = ws[2 * up + 1];
#pragma unroll
                for (int rr = 0; rr < 4; rr++) {
                    float lo, hi; unpk(acc[up * 4 + rr], lo, hi);
                    float h2a = fmaxf(lo + b2a, 0.f);
                    float h2b = fmaxf(hi + b2b, 0.f);
                    muP[rr] += h2a * wma + h2b * wmb;
                    scP[rr] += h2a * wsa + h2b * wsb;
                }
            }
            // reduce over the 8 ull lanes within each rg octet
#pragma unroll
            for (int off = 4; off > 0; off >>= 1) {
#pragma unroll
                for (int rr = 0; rr < 4; rr++) {
                    muP[rr] += __shfl_xor_sync(0xffffffffu, muP[rr], off);
                    scP[rr] += __shfl_xor_sync(0xffffffffu, scP[rr], off);
                }
            }
            if (ull == 0) {
#pragma unroll
                for (int rr = 0; rr < 4; rr++) {
                    int r = half * 16 + rg * 4 + rr;
                    red[blk * 64 + r * 2]     = muP[rr];
                    red[blk * 64 + r * 2 + 1] = scP[rr];
                }
            }
        }
        __syncthreads();

        if (t < ROWS) {
            const int na = (ncur + 63) >> 6;
            int r = t;
            float mu = bo[i], ps = bo[DN + i];
            for (int b = 0; b < na; b++) {
                mu += red[b * 64 + r * 2];
                ps += red[b * 64 + r * 2 + 1];
            }
            float sc = fmaxf(ps, 0.f) + log1pf(expf(-fabsf(ps)));   // stable softplus
            int bb = row0 + r;
            float z = mu + sc * eps[bb * DN + i];
            out[bb * DN + i]               = z;
            out[BN * DN + bb * DN + i]     = mu;
            out[2 * BN * DN + bb * DN + i] = sc;
            zbuf[r] = z;
        }
        __syncthreads();

        // rank-1 a1 update on suffix [ncur, HN); freeze-relu slice [ncur, nfreeze)
        if (i < DN - 1) {
            const int nfreeze = cntd(i + 1);
            const int rem = HN - ncur;
            const float* w1 = g_W1r + i * HN;
            for (int idx = t; idx < rem * (ROWS / 2); idx += NTHR) {
                int p  = ncur + (idx >> 4);
                int rp = idx & 15;
                float w = w1[p];
                float2* a = (float2*)&a1f[p * ROWS + 2 * rp];
                float2 zz = *(const float2*)&zbuf[2 * rp];
                float2 av = *a;
                av.x = fmaf(zz.x, w, av.x);
                av.y = fmaf(zz.y, w, av.y);
                if (p < nfreeze) {          // freezes now: apply relu permanently
                    av.x = fmaxf(av.x, 0.f);
                    av.y = fmaxf(av.y, 0.f);
                }
                *a = av;
            }
            __syncthreads();
        }
    }
}

// ------------- launch ---------------------------------------------------------
extern "C" void kernel_launch(void* const* d_in, const int* in_sizes, int n_in,
                              void* d_out, int out_size) {
    (void)in_sizes; (void)n_in; (void)out_size;
    const float* ctx = (const float*)d_in[0];
    const float* eps = (const float*)d_in[1];
    const float* W1  = (const float*)d_in[2];
    const float* b1  = (const float*)d_in[3];
    const float* Wc  = (const float*)d_in[4];
    const float* W2  = (const float*)d_in[5];
    const float* b2  = (const float*)d_in[6];
    const float* Wo  = (const float*)d_in[7];
    const float* bo  = (const float*)d_in[8];
    float* out = (float*)d_out;

    prep_kernel<<<(HN * HN + 255) / 256, 256>>>(W1, b1, Wc, W2, b2, Wo);

    // smem: a1f 16384 + zbuf 32 + red 512 + pad
    const int smem_bytes = (HN * ROWS + ROWS + 512 + 64) * (int)sizeof(float);
    cudaFuncSetAttribute(made_kernel, cudaFuncAttributeMaxDynamicSharedMemorySize, smem_bytes);
    made_kernel<<<BN / ROWS, NTHR, smem_bytes>>>(ctx, eps, bo, out);
}

// round 12
// speedup vs baseline: 6.8666x; 6.8666x over previous
#include <cuda_runtime.h>
#include <math.h>

// Problem constants
#define BN   8192
#define DN   64
#define CTXN 256
#define HN   512
#define ROWS 32        // rows per CTA
#define NTHR 256
#define CTXP 36        // padded row-stride for staged context (144B, 16B-aligned)

typedef unsigned long long u64;

// ---------------- static device scratch (no allocations allowed) -------------
__device__ __align__(16) float g_W2r[HN * HN];    // [k_in][n_out], permuted+masked
__device__ __align__(16) float g_W1r[DN * HN];    // [input d][p], permuted+masked
__device__ __align__(16) float g_WomMu[DN * HN];  // [step i][p]
__device__ __align__(16) float g_WomSc[DN * HN];  // [step i][p]
__device__ __align__(16) float g_Wcr[CTXN * HN];  // [c][p] permuted Wc
__device__ __align__(16) float g_b1r[HN];
__device__ __align__(16) float g_b2r[HN];

// ------------- degree-sorted permutation (analytic) --------------------------
// mh[h] = h % 63 + 1 ; degrees 1..8 appear 9x, 9..63 appear 8x.
__device__ __forceinline__ int degp(int p) { return (p < 72) ? (p / 9 + 1) : (p / 8); }
__device__ __forceinline__ int origp(int p) {
    int d, j;
    if (p < 72) { d = p / 9 + 1; j = p - 9 * (d - 1); }
    else        { d = p / 8;     j = p - 8 * d; }
    return (d - 1) + 63 * j;
}
__device__ __forceinline__ int cntd(int d) {
    return (d <= 0) ? 0 : ((d <= 8) ? 9 * d : 8 * d + 8);
}

// ------------- packed f32x2 helpers ------------------------------------------
__device__ __forceinline__ u64 dup2(float a) {
    u64 r; asm("mov.b64 %0, {%1, %1};" : "=l"(r) : "f"(a)); return r;
}
__device__ __forceinline__ void fma2(u64& d, u64 a, u64 b) {
    asm("fma.rn.f32x2 %0, %1, %2, %0;" : "+l"(d) : "l"(a), "l"(b));
}
__device__ __forceinline__ void unpk(u64 v, float& a, float& b) {
    asm("mov.b64 {%0, %1}, %2;" : "=f"(a), "=f"(b) : "l"(v));
}

// ------------- weight preparation (masked, permuted) --------------------------
__global__ void prep_kernel(const float* __restrict__ W1, const float* __restrict__ b1,
                            const float* __restrict__ Wc, const float* __restrict__ W2,
                            const float* __restrict__ b2, const float* __restrict__ Wo) {
    int idx = blockIdx.x * blockDim.x + threadIdx.x;
    if (idx < HN * HN) {
        int k = idx / HN, n = idx % HN;
        int dn = degp(n), dk = degp(k);
        g_W2r[idx] = (dn >= dk) ? W2[origp(n) * HN + origp(k)] : 0.f;
    }
    if (idx < DN * HN) {
        int i = idx / HN, p = idx % HN;
        int dp = degp(p), op = origp(p);
        g_W1r[idx]   = (dp >= i + 1) ? W1[op * DN + i] : 0.f;
        bool m = (dp <= i);
        g_WomMu[idx] = m ? Wo[i * HN + op] : 0.f;
        g_WomSc[idx] = m ? Wo[(DN + i) * HN + op] : 0.f;
    }
    if (idx < CTXN * HN) {
        int c = idx / HN, p = idx % HN;
        g_Wcr[idx] = Wc[origp(p) * CTXN + c];
    }
    if (idx < HN) {
        int op = origp(idx);
        g_b1r[idx] = b1[op];
        g_b2r[idx] = b2[op];
    }
}

// one k-row of weights for this lane's 8 units
struct G2 { ulonglong2 a, b; };
__device__ __forceinline__ void loadW(G2& g, const float* wp) {
    g.a = *(const ulonglong2*)(wp);
    g.b = *(const ulonglong2*)(wp + 4);
}

// ------------- main persistent kernel ----------------------------------------
// Incremental MADE: running accumulator S[n][r] = sum_{k<cntd(i)} relu(a1[k]) *
// W2r[k][n] lives in registers; each step adds only the Delta-k newly frozen
// rows (each of the 512 k-rows is processed exactly once over all 64 steps).
// Warp wid owns unit block [wid*64, wid*64+64). lane = rg*8+ull:
//   ull = lane&7 -> 8 units (4 f32x2 pairs), rg = lane>>3 -> 8 rows.
__global__ void __launch_bounds__(NTHR, 2)
made_kernel(const float* __restrict__ ctx, const float* __restrict__ eps,
            const float* __restrict__ bo, float* __restrict__ out) {
    extern __shared__ float smem[];
    float* a1f  = smem;                    // [HN][ROWS]: prefix relu'd, suffix raw
    float* epsS = smem + HN * ROWS;        // [ROWS][DN]
    float* oZ   = epsS + ROWS * DN;        // [ROWS][DN]
    float* oMu  = oZ   + ROWS * DN;        // [ROWS][DN]
    float* oSc  = oMu  + ROWS * DN;        // [ROWS][DN]
    float* zbuf = oSc  + ROWS * DN;        // [ROWS]
    float* red  = zbuf + ROWS;             // [8 blk][32 row][2]

    const int t    = threadIdx.x;
    const int wid  = t >> 5;
    const int lane = t & 31;
    const int rg   = lane >> 3;
    const int ull  = lane & 7;
    const int blk  = wid;
    const int nb   = blk * 64 + ull * 8;   // this lane's 8 units
    const int r0t  = rg * 8;               // this lane's 8 rows
    const int row0 = blockIdx.x * ROWS;

    // ---- Phase 0: stage context (transposed, stride CTXP) + eps ----
    for (int idx = t; idx < CTXN * ROWS; idx += NTHR) {
        int r = idx >> 8;
        int c = idx & 255;
        a1f[c * CTXP + r] = ctx[(row0 + r) * CTXN + c];
    }
    for (int idx = t; idx < ROWS * DN; idx += NTHR)
        epsS[idx] = eps[row0 * DN + idx];
    __syncthreads();

    // ---- Phase 1: ctx GEMM -> a1 init (raw, +b1) ----
    {
        u64 acc1[4][8];
#pragma unroll
        for (int a = 0; a < 4; a++)
#pragma unroll
            for (int b = 0; b < 8; b++) acc1[a][b] = 0ull;
        const float* wp = g_Wcr + nb;
        const float* hp = a1f + r0t;
#pragma unroll 2
        for (int c = 0; c < CTXN; c++) {
            ulonglong2 wA = *(const ulonglong2*)(wp);
            ulonglong2 wB = *(const ulonglong2*)(wp + 4);
            wp += HN;
            float4 v0 = *(const float4*)(hp);
            float4 v1 = *(const float4*)(hp + 4);
            hp += CTXP;
            u64 h[8];
            h[0] = dup2(v0.x); h[1] = dup2(v0.y); h[2] = dup2(v0.z); h[3] = dup2(v0.w);
            h[4] = dup2(v1.x); h[5] = dup2(v1.y); h[6] = dup2(v1.z); h[7] = dup2(v1.w);
#pragma unroll
            for (int r = 0; r < 8; r++) {
                fma2(acc1[0][r], wA.x, h[r]);
                fma2(acc1[1][r], wA.y, h[r]);
                fma2(acc1[2][r], wB.x, h[r]);
                fma2(acc1[3][r], wB.y, h[r]);
            }
        }
        __syncthreads();
#pragma unroll
        for (int up = 0; up < 4; up++) {
            int n0 = nb + 2 * up;
            float bA = g_b1r[n0], bB = g_b1r[n0 + 1];
#pragma unroll
            for (int rr = 0; rr < 8; rr++) {
                float lo, hi; unpk(acc1[up][rr], lo, hi);
                int r = r0t + rr;
                a1f[n0 * ROWS + r]       = lo + bA;
                a1f[(n0 + 1) * ROWS + r] = hi + bB;
            }
        }
    }
    __syncthreads();

    // ---- Phase 2: D sequential steps with incremental S ----
    // S[up][rr]: unit-pair up (0..3) x row rr (0..7), persistent accumulator.
    u64 S[4][8];
#pragma unroll
    for (int a = 0; a < 4; a++)
#pragma unroll
        for (int b = 0; b < 8; b++) S[a][b] = 0ull;

    const float2 zzc_init = {0.f, 0.f}; (void)zzc_init;
    // distance-2 pipelined weight stream over global k = 0..511
    G2 s0, s1;
    loadW(s0, g_W2r + 0 * HN + nb);
    loadW(s1, g_W2r + 1 * HN + nb);

    int kprev = 0;
    for (int i = 0; i < DN; i++) {
        const int ncur = cntd(i);
        const int kst = kprev, ken = ncur;
        kprev = ncur;

        // -- S update with newly frozen rows [kst, ken) --
        {
            const float* hp = a1f + kst * ROWS + r0t;
#pragma unroll 1
            for (int k = kst; k < ken; k++) {
                G2 cur = s0;
                s0 = s1;
                int kl = k + 2; kl = (kl > HN - 1) ? (HN - 1) : kl;
                loadW(s1, g_W2r + kl * HN + nb);
                float4 v0 = *(const float4*)(hp);
                float4 v1 = *(const float4*)(hp + 4);
                hp += ROWS;
                u64 h[8];
                h[0] = dup2(v0.x); h[1] = dup2(v0.y); h[2] = dup2(v0.z); h[3] = dup2(v0.w);
                h[4] = dup2(v1.x); h[5] = dup2(v1.y); h[6] = dup2(v1.z); h[7] = dup2(v1.w);
#pragma unroll
                for (int r = 0; r < 8; r++) {
                    fma2(S[0][r], cur.a.x, h[r]);
                    fma2(S[1][r], cur.a.y, h[r]);
                    fma2(S[2][r], cur.b.x, h[r]);
                    fma2(S[3][r], cur.b.y, h[r]);
                }
            }
        }

        // -- epilogue: +b2, relu, dot with Wom mu/sc (masked weights handle act) --
        {
            float muP[8], scP[8];
#pragma unroll
            for (int r = 0; r < 8; r++) { muP[r] = 0.f; scP[r] = 0.f; }
            const float* wm = g_WomMu + i * HN + nb;
            const float* ws = g_WomSc + i * HN + nb;
#pragma unroll
            for (int up = 0; up < 4; up++) {
                int n0 = nb + 2 * up;
                float b2a = g_b2r[n0], b2b = g_b2r[n0 + 1];
                float wma = wm[2 * up], wmb = wm[2 * up + 1];
                float wsa = ws[2 * up], wsb = ws[2 * up + 1];
#pragma unroll
                for (int rr = 0; rr < 8; rr++) {
                    float lo, hi; unpk(S[up][rr], lo, hi);
                    float h2a = fmaxf(lo + b2a, 0.f);
                    float h2b = fmaxf(hi + b2b, 0.f);
                    muP[rr] += h2a * wma + h2b * wmb;
                    scP[rr] += h2a * wsa + h2b * wsb;
                }
            }
            // reduce over the 8 ull lanes (xor within octet)
#pragma unroll
            for (int off = 4; off > 0; off >>= 1) {
#pragma unroll
                for (int rr = 0; rr < 8; rr++) {
                    muP[rr] += __shfl_xor_sync(0xffffffffu, muP[rr], off);
                    scP[rr] += __shfl_xor_sync(0xffffffffu, scP[rr], off);
                }
            }
            if (ull == 0) {
#pragma unroll
                for (int rr = 0; rr < 8; rr++) {
                    int r = r0t + rr;
                    red[blk * 64 + r * 2]     = muP[rr];
                    red[blk * 64 + r * 2 + 1] = scP[rr];
                }
            }
        }
        __syncthreads();

        if (t < ROWS) {
            int r = t;
            float mu = bo[i], ps = bo[DN + i];
#pragma unroll
            for (int b = 0; b < 8; b++) {
                mu += red[b * 64 + r * 2];
                ps += red[b * 64 + r * 2 + 1];
            }
            float sc = fmaxf(ps, 0.f) + log1pf(expf(-fabsf(ps)));   // stable softplus
            float z = mu + sc * epsS[r * DN + i];
            oZ[r * DN + i]  = z;
            oMu[r * DN + i] = mu;
            oSc[r * DN + i] = sc;
            zbuf[r] = z;
        }
        __syncthreads();

        // rank-1 a1 update on suffix [ncur, HN); freeze-relu slice [ncur, nfreeze)
        if (i < DN - 1) {
            const int nfreeze = cntd(i + 1);
            const int rem = HN - ncur;
            const float* w1 = g_W1r + i * HN;
            const float2 zz = *(const float2*)&zbuf[2 * (t & 15)];  // rp = t&15 fixed
            for (int idx = t; idx < rem * (ROWS / 2); idx += NTHR) {
                int p = ncur + (idx >> 4);
                float w = w1[p];
                float2* a = (float2*)&a1f[p * ROWS + 2 * (t & 15)];
                float2 av = *a;
                av.x = fmaf(zz.x, w, av.x);
                av.y = fmaf(zz.y, w, av.y);
                if (p < nfreeze) {          // freezes now: apply relu permanently
                    av.x = fmaxf(av.x, 0.f);
                    av.y = fmaxf(av.y, 0.f);
                }
                *a = av;
            }
        }
        __syncthreads();
    }

    // ---- Phase 3: coalesced output writeback ----
    for (int idx = t; idx < ROWS * DN; idx += NTHR) {
        int r = idx >> 6, d = idx & 63;
        int g = (row0 + r) * DN + d;
        out[g]               = oZ[idx];
        out[BN * DN + g]     = oMu[idx];
        out[2 * BN * DN + g] = oSc[idx];
    }
}

// ------------- launch ---------------------------------------------------------
extern "C" void kernel_launch(void* const* d_in, const int* in_sizes, int n_in,
                              void* d_out, int out_size) {
    (void)in_sizes; (void)n_in; (void)out_size;
    const float* ctx = (const float*)d_in[0];
    const float* eps = (const float*)d_in[1];
    const float* W1  = (const float*)d_in[2];
    const float* b1  = (const float*)d_in[3];
    const float* Wc  = (const float*)d_in[4];
    const float* W2  = (const float*)d_in[5];
    const float* b2  = (const float*)d_in[6];
    const float* Wo  = (const float*)d_in[7];
    const float* bo  = (const float*)d_in[8];
    float* out = (float*)d_out;

    prep_kernel<<<(HN * HN + 255) / 256, 256>>>(W1, b1, Wc, W2, b2, Wo);

    // smem: a1f 16384 + epsS 2048 + out bufs 3*2048 + zbuf 32 + red 512 + pad
    const int smem_bytes = (HN * ROWS + 4 * ROWS * DN + ROWS + 512 + 64) * (int)sizeof(float);
    cudaFuncSetAttribute(made_kernel, cudaFuncAttributeMaxDynamicSharedMemorySize, smem_bytes);
    made_kernel<<<BN / ROWS, NTHR, smem_bytes>>>(ctx, eps, bo, out);
}